// round 1
// baseline (speedup 1.0000x reference)
#include <cuda_runtime.h>

// ----------------------------------------------------------------------------
// EBTBlock (DiT adaLN-Zero block): B=8, S=1024, D=1024, H=16, DH=64, fp32.
// Round 0: correct baseline. SIMT fp32 SGEMM (128x128x16, 8x8/thread) with
// fused epilogues + small fused LN/mods/softmax kernels.
// ----------------------------------------------------------------------------

#define B_    8
#define S_    1024
#define D_    1024
#define H_    16
#define DH_   64
#define M_    (B_ * S_)      // 8192 token rows
#define SIXD_ (6 * D_)       // 6144

// Scratch (device globals; no allocation allowed in kernel_launch)
__device__ float g_mods[B_ * SIXD_];            // [8, 6144]
__device__ float g_xm[M_ * D_];                 // modulated LN output
__device__ float g_qkv[M_ * 3 * D_];            // [8192, 3072]
__device__ float g_scores[134217728];           // [B*H, 1024, 1024] = 512 MB
__device__ float g_o[M_ * D_];                  // attention output (B,S,D)
__device__ float g_hbuf[M_ * 4 * D_];           // fc1 activations [8192, 4096]

// ---------------------------------------------------------------------------
// block reductions (assumes 256 threads = 8 warps)
// ---------------------------------------------------------------------------
__device__ __forceinline__ float blk_reduce_sum(float v, float* red) {
    int lane = threadIdx.x & 31, w = threadIdx.x >> 5;
#pragma unroll
    for (int o = 16; o; o >>= 1) v += __shfl_xor_sync(0xffffffffu, v, o);
    if (lane == 0) red[w] = v;
    __syncthreads();
    if (w == 0) {
        v = (lane < 8) ? red[lane] : 0.0f;
#pragma unroll
        for (int o = 4; o; o >>= 1) v += __shfl_xor_sync(0xffffffffu, v, o);
        if (lane == 0) red[0] = v;
    }
    __syncthreads();
    float r = red[0];
    __syncthreads();
    return r;
}

__device__ __forceinline__ float blk_reduce_max(float v, float* red) {
    int lane = threadIdx.x & 31, w = threadIdx.x >> 5;
#pragma unroll
    for (int o = 16; o; o >>= 1) v = fmaxf(v, __shfl_xor_sync(0xffffffffu, v, o));
    if (lane == 0) red[w] = v;
    __syncthreads();
    if (w == 0) {
        v = (lane < 8) ? red[lane] : -3.4e38f;
#pragma unroll
        for (int o = 4; o; o >>= 1) v = fmaxf(v, __shfl_xor_sync(0xffffffffu, v, o));
        if (lane == 0) red[0] = v;
    }
    __syncthreads();
    float r = red[0];
    __syncthreads();
    return r;
}

__device__ __forceinline__ float gelu_tanh(float x) {
    float x3 = x * x * x;
    float t = tanhf(0.7978845608028654f * (x + 0.044715f * x3));
    return 0.5f * x * (1.0f + t);
}

// ---------------------------------------------------------------------------
// adaLN modulation: mods[b, j] = dot(silu(y[b,:]), w_adaln[j,:]) + b_adaln[j]
// grid (B_, 6144/256), 256 threads
// ---------------------------------------------------------------------------
__global__ void mods_kernel(const float* __restrict__ y,
                            const float* __restrict__ w,
                            const float* __restrict__ bias,
                            float* __restrict__ mods) {
    __shared__ float sy[D_];
    int b = blockIdx.x;
    int tid = threadIdx.x;
    float4 yv = ((const float4*)(y + b * D_))[tid];
    sy[tid * 4 + 0] = yv.x / (1.0f + expf(-yv.x));
    sy[tid * 4 + 1] = yv.y / (1.0f + expf(-yv.y));
    sy[tid * 4 + 2] = yv.z / (1.0f + expf(-yv.z));
    sy[tid * 4 + 3] = yv.w / (1.0f + expf(-yv.w));
    __syncthreads();

    int j = blockIdx.y * 256 + tid;
    float acc = bias[j];
    const float4* w4 = (const float4*)(w + (long)j * D_);
#pragma unroll 8
    for (int k = 0; k < D_ / 4; k++) {
        float4 wv = w4[k];
        acc += sy[4 * k + 0] * wv.x + sy[4 * k + 1] * wv.y +
               sy[4 * k + 2] * wv.z + sy[4 * k + 3] * wv.w;
    }
    mods[b * SIXD_ + j] = acc;
}

// ---------------------------------------------------------------------------
// Fused LayerNorm (no affine) + adaLN modulate: out = ln(x)*(1+sc) + sh
// one block (256 thr) per token row
// ---------------------------------------------------------------------------
__global__ void ln_mod_kernel(const float* __restrict__ X,
                              const float* __restrict__ mods,
                              int sh_off, int sc_off,
                              float* __restrict__ out) {
    __shared__ float red[32];
    long row = blockIdx.x;
    int b = (int)(row >> 10);    // S_ = 1024
    int tid = threadIdx.x;
    float4 v = ((const float4*)(X + row * D_))[tid];

    float s = v.x + v.y + v.z + v.w;
    s = blk_reduce_sum(s, red);
    float mean = s * (1.0f / D_);

    float dx = v.x - mean, dy = v.y - mean, dz = v.z - mean, dw = v.w - mean;
    float sq = dx * dx + dy * dy + dz * dz + dw * dw;
    sq = blk_reduce_sum(sq, red);
    float inv = rsqrtf(sq * (1.0f / D_) + 1e-5f);

    const float* mrow = mods + b * SIXD_;
    int c = tid * 4;
    float4 o;
    o.x = dx * inv * (1.0f + mrow[sc_off + c + 0]) + mrow[sh_off + c + 0];
    o.y = dy * inv * (1.0f + mrow[sc_off + c + 1]) + mrow[sh_off + c + 1];
    o.z = dz * inv * (1.0f + mrow[sc_off + c + 2]) + mrow[sh_off + c + 2];
    o.w = dw * inv * (1.0f + mrow[sc_off + c + 3]) + mrow[sh_off + c + 3];
    ((float4*)(out + row * D_))[tid] = o;
}

// ---------------------------------------------------------------------------
// In-place row softmax over 1024 columns. one block (256 thr) per row.
// ---------------------------------------------------------------------------
__global__ void softmax_kernel(float* __restrict__ sc) {
    __shared__ float red[32];
    long row = blockIdx.x;
    float4* p = (float4*)(sc + row * (long)S_);
    int tid = threadIdx.x;
    float4 v = p[tid];
    float mx = fmaxf(fmaxf(v.x, v.y), fmaxf(v.z, v.w));
    mx = blk_reduce_max(mx, red);
    float4 e;
    e.x = expf(v.x - mx); e.y = expf(v.y - mx);
    e.z = expf(v.z - mx); e.w = expf(v.w - mx);
    float s = e.x + e.y + e.z + e.w;
    s = blk_reduce_sum(s, red);
    float inv = 1.0f / s;
    e.x *= inv; e.y *= inv; e.z *= inv; e.w *= inv;
    p[tid] = e;
}

// ---------------------------------------------------------------------------
// Generic batched SGEMM: C = epilogue(alpha * A @ op(B))
//   A: [M,K] row-major, lda
//   B: NT mode (BNN=false): [N,K] row-major (weights)   C[m,n]=sum A[m,k]B[n,k]
//      NN mode (BNN=true):  [K,N] row-major             C[m,n]=sum A[m,k]B[k,n]
//   batching: z -> (bb = z/nH, hh = z%nH); ptr += bb*s?b + hh*s?h
//   EPI 0: C = alpha*acc
//   EPI 1: C = gelu(acc + bias[n])
//   EPI 2: C = resid[m,n] + gate[(m/rows_per_b)*gstride + n] * (acc + bias[n])
// Tiles: 128x128x16, 256 threads, 8x8 per thread.
// Requires: M % 128 == 0, K % 16 == 0, N % 4 == 0, ld* % 4 == 0.
// ---------------------------------------------------------------------------
template <int EPI, bool BNN>
__global__ __launch_bounds__(256)
void gemm_kernel(const float* __restrict__ A, int lda, long sAb, long sAh,
                 const float* __restrict__ B, int ldb, long sBb, long sBh,
                 float* __restrict__ C, int ldc, long sCb, long sCh,
                 int M, int N, int K, int nH, float alpha,
                 const float* __restrict__ bias,
                 const float* __restrict__ resid,
                 const float* __restrict__ gate,
                 int gstride, int rows_per_b) {
    __shared__ float As[16][132];
    __shared__ float Bs[16][132];

    int z = blockIdx.z;
    int bb = z / nH, hh = z % nH;
    A += (long)bb * sAb + (long)hh * sAh;
    B += (long)bb * sBb + (long)hh * sBh;
    C += (long)bb * sCb + (long)hh * sCh;

    int tid = threadIdx.x;
    int tx = tid & 15, ty = tid >> 4;
    int m0 = blockIdx.y * 128, n0 = blockIdx.x * 128;

    int a_row = tid >> 2;            // 0..63
    int a_c4  = (tid & 3) * 4;       // 0,4,8,12
    int b_kk  = tid >> 5;            // 0..7  (NN loader)
    int b_v4  = (tid & 31) * 4;      // 0..124

    float acc[8][8];
#pragma unroll
    for (int i = 0; i < 8; i++)
#pragma unroll
        for (int j = 0; j < 8; j++) acc[i][j] = 0.0f;

    for (int k0 = 0; k0 < K; k0 += 16) {
#pragma unroll
        for (int i = 0; i < 2; i++) {
            int r = a_row + i * 64;
            float4 v = *(const float4*)(A + (long)(m0 + r) * lda + k0 + a_c4);
            As[a_c4 + 0][r] = v.x; As[a_c4 + 1][r] = v.y;
            As[a_c4 + 2][r] = v.z; As[a_c4 + 3][r] = v.w;
        }
        if (!BNN) {
#pragma unroll
            for (int i = 0; i < 2; i++) {
                int r = a_row + i * 64;   // n index within tile
                float4 v = make_float4(0.f, 0.f, 0.f, 0.f);
                if (n0 + r < N)
                    v = *(const float4*)(B + (long)(n0 + r) * ldb + k0 + a_c4);
                Bs[a_c4 + 0][r] = v.x; Bs[a_c4 + 1][r] = v.y;
                Bs[a_c4 + 2][r] = v.z; Bs[a_c4 + 3][r] = v.w;
            }
        } else {
#pragma unroll
            for (int i = 0; i < 2; i++) {
                int kk = b_kk + i * 8;
                float4 v = make_float4(0.f, 0.f, 0.f, 0.f);
                if (n0 + b_v4 < N)
                    v = *(const float4*)(B + (long)(k0 + kk) * ldb + n0 + b_v4);
                *(float4*)&Bs[kk][b_v4] = v;
            }
        }
        __syncthreads();

#pragma unroll
        for (int kk = 0; kk < 16; kk++) {
            float a[8], b[8];
            *(float4*)&a[0] = *(const float4*)&As[kk][ty * 8];
            *(float4*)&a[4] = *(const float4*)&As[kk][ty * 8 + 4];
            *(float4*)&b[0] = *(const float4*)&Bs[kk][tx * 4];
            *(float4*)&b[4] = *(const float4*)&Bs[kk][64 + tx * 4];
#pragma unroll
            for (int i = 0; i < 8; i++)
#pragma unroll
                for (int j = 0; j < 8; j++)
                    acc[i][j] += a[i] * b[j];
        }
        __syncthreads();
    }

    // epilogue
#pragma unroll
    for (int i = 0; i < 8; i++) {
        int gm = m0 + ty * 8 + i;
        int bm = gm / rows_per_b;
#pragma unroll
        for (int g = 0; g < 2; g++) {
            int gn = n0 + g * 64 + tx * 4;
            if (gn >= N) continue;    // N % 4 == 0, gn % 4 == 0 -> whole vec ok
            float4 r;
            float* rv = &r.x;
#pragma unroll
            for (int jj = 0; jj < 4; jj++) {
                float v = acc[i][g * 4 + jj] * alpha;
                if (EPI == 1) {
                    v = gelu_tanh(v + bias[gn + jj]);
                } else if (EPI == 2) {
                    v = resid[(long)gm * ldc + gn + jj] +
                        gate[(long)bm * gstride + gn + jj] * (v + bias[gn + jj]);
                }
                rv[jj] = v;
            }
            *(float4*)(C + (long)gm * ldc + gn) = r;
        }
    }
}

// ---------------------------------------------------------------------------
// host launcher
// ---------------------------------------------------------------------------
extern "C" void kernel_launch(void* const* d_in, const int* in_sizes, int n_in,
                              void* d_out, int out_size) {
    const float* x       = (const float*)d_in[0];
    const float* y       = (const float*)d_in[1];
    const float* w_adaln = (const float*)d_in[2];
    const float* b_adaln = (const float*)d_in[3];
    const float* w_qkv   = (const float*)d_in[4];
    const float* w_proj  = (const float*)d_in[5];
    const float* b_proj  = (const float*)d_in[6];
    const float* w_fc1   = (const float*)d_in[7];
    const float* b_fc1   = (const float*)d_in[8];
    const float* w_fc2   = (const float*)d_in[9];
    const float* b_fc2   = (const float*)d_in[10];
    float* out = (float*)d_out;

    float *mods_p, *xm_p, *qkv_p, *scores_p, *o_p, *h_p;
    cudaGetSymbolAddress((void**)&mods_p,   g_mods);
    cudaGetSymbolAddress((void**)&xm_p,     g_xm);
    cudaGetSymbolAddress((void**)&qkv_p,    g_qkv);
    cudaGetSymbolAddress((void**)&scores_p, g_scores);
    cudaGetSymbolAddress((void**)&o_p,      g_o);
    cudaGetSymbolAddress((void**)&h_p,      g_hbuf);

    const long SQb = (long)S_ * 3 * D_;       // qkv batch stride (per b)
    const long SCb = (long)H_ * S_ * S_;      // scores batch stride (per b)
    const long SCh = (long)S_ * S_;           // scores head stride

    // 1) adaLN modulation params
    mods_kernel<<<dim3(B_, SIXD_ / 256), 256>>>(y, w_adaln, b_adaln, mods_p);

    // 2) LN(x) * (1+sc_a) + sh_a
    ln_mod_kernel<<<M_, 256>>>(x, mods_p, 0 * D_, 1 * D_, xm_p);

    // 3) qkv = xm @ w_qkv^T           [8192, 3072]
    gemm_kernel<0, false><<<dim3(3 * D_ / 128, M_ / 128, 1), 256>>>(
        xm_p, D_, 0, 0, w_qkv, D_, 0, 0, qkv_p, 3 * D_, 0, 0,
        M_, 3 * D_, D_, 1, 1.0f, nullptr, nullptr, nullptr, 0, S_);

    // 4) scores = scale * q @ k^T      per (b,h), 128 batches
    gemm_kernel<0, false><<<dim3(S_ / 128, S_ / 128, B_ * H_), 256>>>(
        qkv_p, 3 * D_, SQb, DH_,
        qkv_p + D_, 3 * D_, SQb, DH_,
        scores_p, S_, SCb, SCh,
        S_, S_, DH_, H_, 0.125f, nullptr, nullptr, nullptr, 0, S_);

    // 5) softmax rows
    softmax_kernel<<<B_ * H_ * S_, 256>>>(scores_p);

    // 6) o = attn @ v  (NN, N=64), scattered into (B,S,D) layout
    gemm_kernel<0, true><<<dim3(1, S_ / 128, B_ * H_), 256>>>(
        scores_p, S_, SCb, SCh,
        qkv_p + 2 * D_, 3 * D_, SQb, DH_,
        o_p, D_, (long)S_ * D_, DH_,
        S_, DH_, S_, H_, 1.0f, nullptr, nullptr, nullptr, 0, S_);

    // 7) x1 = x + g_a * (o @ w_proj^T + b_proj)   -> d_out
    gemm_kernel<2, false><<<dim3(D_ / 128, M_ / 128, 1), 256>>>(
        o_p, D_, 0, 0, w_proj, D_, 0, 0, out, D_, 0, 0,
        M_, D_, D_, 1, 1.0f, b_proj, x, mods_p + 2 * D_, SIXD_, S_);

    // 8) LN(x1) * (1+sc_m) + sh_m
    ln_mod_kernel<<<M_, 256>>>(out, mods_p, 3 * D_, 4 * D_, xm_p);

    // 9) h = gelu(xm @ w_fc1^T + b_fc1)   [8192, 4096]
    gemm_kernel<1, false><<<dim3(4 * D_ / 128, M_ / 128, 1), 256>>>(
        xm_p, D_, 0, 0, w_fc1, D_, 0, 0, h_p, 4 * D_, 0, 0,
        M_, 4 * D_, D_, 1, 1.0f, b_fc1, nullptr, nullptr, 0, S_);

    // 10) out = x1 + g_m * (h @ w_fc2^T + b_fc2)
    gemm_kernel<2, false><<<dim3(D_ / 128, M_ / 128, 1), 256>>>(
        h_p, 4 * D_, 0, 0, w_fc2, 4 * D_, 0, 0, out, D_, 0, 0,
        M_, D_, 4 * D_, 1, 1.0f, b_fc2, out, mods_p + 5 * D_, SIXD_, S_);
}

// round 3
// speedup vs baseline: 2.7552x; 2.7552x over previous
#include <cuda_runtime.h>
#include <cstdint>

// ----------------------------------------------------------------------------
// EBTBlock (DiT adaLN-Zero): B=8, S=1024, D=1024, H=16, DH=64, fp32.
// Round 3: all GEMMs via mma.sync.m16n8k8 tf32 (base-target tensor path,
// tcgen05 unavailable: harness PTX targets sm_103 not sm_103a).
// Operands pre-rounded to tf32 (cvt.rna) by producers -> cp.async double-
// buffered GEMM loaders, bank-conflict-free padded SMEM.
// ----------------------------------------------------------------------------

#define B_    8
#define S_    1024
#define D_    1024
#define H_    16
#define DH_   64
#define M_    (B_ * S_)
#define SIXD_ (6 * D_)

// Scratch
__device__ float g_mods[B_ * SIXD_];
__device__ float g_xm[M_ * D_];
__device__ float g_qkv[M_ * 3 * D_];
__device__ float g_scores[134217728];     // [B*H,1024,1024] 512MB
__device__ float g_o[M_ * D_];
__device__ float g_hbuf[M_ * 4 * D_];
__device__ float g_w[12 * 1024 * 1024];   // rounded weights: qkv|proj|fc1|fc2

// ===========================================================================
// helpers
// ===========================================================================
__device__ __forceinline__ uint32_t smem_u32(const void* p) {
    uint32_t a;
    asm("{ .reg .u64 t; cvta.to.shared.u64 t, %1; cvt.u32.u64 %0, t; }"
        : "=r"(a) : "l"(p));
    return a;
}
__device__ __forceinline__ float round_tf32(float f) {
    uint32_t u;
    asm("cvt.rna.tf32.f32 %0, %1;" : "=r"(u) : "f"(f));
    return __uint_as_float(u);
}
__device__ __forceinline__ void cpasync16(uint32_t dst, const void* src) {
    asm volatile("cp.async.ca.shared.global [%0], [%1], 16;"
                 :: "r"(dst), "l"(src) : "memory");
}
__device__ __forceinline__ void mma_tf32(float* d, const uint32_t* a,
                                         const uint32_t* b) {
    asm volatile(
        "mma.sync.aligned.m16n8k8.row.col.f32.tf32.tf32.f32 "
        "{%0,%1,%2,%3}, {%4,%5,%6,%7}, {%8,%9}, {%0,%1,%2,%3};"
        : "+f"(d[0]), "+f"(d[1]), "+f"(d[2]), "+f"(d[3])
        : "r"(a[0]), "r"(a[1]), "r"(a[2]), "r"(a[3]), "r"(b[0]), "r"(b[1]));
}
__device__ __forceinline__ float gelu_tanh(float x) {
    float x3 = x * x * x;
    float t = tanhf(0.7978845608028654f * (x + 0.044715f * x3));
    return 0.5f * x * (1.0f + t);
}

// ===========================================================================
// tf32 mma GEMM.  C[m,n] = epi(alpha * sum_k A[m,k]*B'[k,n])
//   NT (!BNN): B is [N,K] row-major (weights / k-rows)
//   NN ( BNN): B is [K,N] row-major, requires N - n0 == 64 (PV head tile)
// tile 128x128, 8 warps (warp tile 32x64), K chunk 32, cp.async 2-stage.
// EPI 0: v    EPI 1: gelu(v+bias[n])    EPI 2: resid + gate[b,n]*(v+bias[n])
// RND: round output to tf32 (it feeds a later GEMM).
// dyn smem: 2 stages * (A 4608 + B 4608 floats) = 73728 B
// ===========================================================================
#define GM_SMEM 73728
#define STG_F   9216
#define STRA    36
#define STRBNN  68

template <int EPI, bool BNN, bool RND>
__global__ __launch_bounds__(256, 2)
void gemm_mma(const float* __restrict__ A, int lda, long sAb, long sAh,
              const float* __restrict__ Bw, int ldb, long sBb, long sBh,
              float* __restrict__ C, int ldc, long sCb, long sCh,
              int N, int K, int nH, float alpha,
              const float* __restrict__ bias,
              const float* __restrict__ resid,
              const float* __restrict__ gate) {
    extern __shared__ float smem[];
    const int tid = threadIdx.x, lane = tid & 31, wid = tid >> 5;
    const int wm = wid & 3, wn = wid >> 2;           // 4x2 warp grid
    const int m0 = blockIdx.y * 128, n0 = blockIdx.x * 128;
    const uint32_t sbase = smem_u32(smem);

    {   // batching
        int z = blockIdx.z;
        int bb = z / nH, hh = z - bb * nH;
        A  += (long)bb * sAb + (long)hh * sAh;
        Bw += (long)bb * sBb + (long)hh * sBh;
        C  += (long)bb * sCb + (long)hh * sCh;
    }

    // warp n coverage (PV: warps with n >= N do nothing)
    int nrem = N - n0 - wn * 64;
    const int nj = nrem >= 64 ? 8 : (nrem <= 0 ? 0 : (nrem >> 3));

    float acc[2][8][4];
#pragma unroll
    for (int i = 0; i < 2; i++)
#pragma unroll
        for (int j = 0; j < 8; j++)
#pragma unroll
            for (int e = 0; e < 4; e++) acc[i][j][e] = 0.0f;

    const int nch = K >> 5;

    auto load_stage = [&](int s, int k0) {
#pragma unroll
        for (int it = 0; it < 4; it++) {           // A: 128 rows x 8 f4
            int idx = tid + it * 256;
            int r = idx >> 3, c4 = (idx & 7) << 2;
            cpasync16(sbase + (uint32_t)(s * STG_F + r * STRA + c4) * 4,
                      A + (size_t)(m0 + r) * lda + k0 + c4);
        }
        if (!BNN) {
#pragma unroll
            for (int it = 0; it < 4; it++) {       // B: 128 n-rows x 8 f4
                int idx = tid + it * 256;
                int r = idx >> 3, c4 = (idx & 7) << 2;
                cpasync16(sbase + (uint32_t)(s * STG_F + 4608 + r * STRA + c4) * 4,
                          Bw + (size_t)(n0 + r) * ldb + k0 + c4);
            }
        } else {
#pragma unroll
            for (int it = 0; it < 2; it++) {       // B: 32 k-rows x 16 f4 (N=64)
                int idx = tid + it * 256;
                int kk = idx >> 4, c4 = (idx & 15) << 2;
                cpasync16(sbase + (uint32_t)(s * STG_F + 4608 + kk * STRBNN + c4) * 4,
                          Bw + (size_t)(k0 + kk) * ldb + n0 + c4);
            }
        }
    };

    load_stage(0, 0);
    asm volatile("cp.async.commit_group;" ::: "memory");

    const int q = lane & 3, lh = lane >> 2;

    for (int i = 0; i < nch; i++) {
        if (i + 1 < nch) {
            load_stage((i + 1) & 1, (i + 1) << 5);
            asm volatile("cp.async.commit_group;" ::: "memory");
            asm volatile("cp.async.wait_group 1;" ::: "memory");
        } else {
            asm volatile("cp.async.wait_group 0;" ::: "memory");
        }
        __syncthreads();

        const uint32_t* sA = (const uint32_t*)(smem + (i & 1) * STG_F);
        const uint32_t* sB = sA + 4608;
#pragma unroll
        for (int kk = 0; kk < 32; kk += 8) {
            uint32_t a[2][4], b[8][2];
#pragma unroll
            for (int ii = 0; ii < 2; ii++) {
                int rowA = wm * 32 + ii * 16 + lh;
                a[ii][0] = sA[rowA * STRA + kk + q];
                a[ii][1] = sA[(rowA + 8) * STRA + kk + q];
                a[ii][2] = sA[rowA * STRA + kk + q + 4];
                a[ii][3] = sA[(rowA + 8) * STRA + kk + q + 4];
            }
#pragma unroll
            for (int j = 0; j < 8; j++) {
                if (j < nj) {
                    int nn = wn * 64 + j * 8 + lh;
                    if (!BNN) {
                        b[j][0] = sB[nn * STRA + kk + q];
                        b[j][1] = sB[nn * STRA + kk + q + 4];
                    } else {
                        b[j][0] = sB[(kk + q) * STRBNN + nn];
                        b[j][1] = sB[(kk + q + 4) * STRBNN + nn];
                    }
                }
            }
#pragma unroll
            for (int ii = 0; ii < 2; ii++)
#pragma unroll
                for (int j = 0; j < 8; j++)
                    if (j < nj) mma_tf32(acc[ii][j], a[ii], b[j]);
        }
        __syncthreads();
    }

    // epilogue
#pragma unroll
    for (int ii = 0; ii < 2; ii++) {
        int gm0 = m0 + wm * 32 + ii * 16 + lh;
#pragma unroll
        for (int j = 0; j < 8; j++) {
            if (j >= nj) continue;
            int gn = n0 + wn * 64 + j * 8 + 2 * q;
#pragma unroll
            for (int h = 0; h < 2; h++) {          // h=0: rows gm0, h=1: gm0+8
                int gm = gm0 + h * 8;
                float2 o;
                float* ov = &o.x;
#pragma unroll
                for (int e = 0; e < 2; e++) {
                    float v = acc[ii][j][h * 2 + e] * alpha;
                    int n = gn + e;
                    if (EPI == 1) {
                        v = gelu_tanh(v + bias[n]);
                    } else if (EPI == 2) {
                        v = resid[(size_t)gm * ldc + n] +
                            gate[(size_t)(gm >> 10) * SIXD_ + n] * (v + bias[n]);
                    }
                    if (RND) v = round_tf32(v);
                    ov[e] = v;
                }
                *(float2*)(C + (size_t)gm * ldc + gn) = o;
            }
        }
    }
}

// ===========================================================================
// block reductions (256 threads)
// ===========================================================================
__device__ __forceinline__ float blk_reduce_sum(float v, float* red) {
    int lane = threadIdx.x & 31, w = threadIdx.x >> 5;
#pragma unroll
    for (int o = 16; o; o >>= 1) v += __shfl_xor_sync(0xffffffffu, v, o);
    if (lane == 0) red[w] = v;
    __syncthreads();
    if (w == 0) {
        v = (lane < 8) ? red[lane] : 0.0f;
#pragma unroll
        for (int o = 4; o; o >>= 1) v += __shfl_xor_sync(0xffffffffu, v, o);
        if (lane == 0) red[0] = v;
    }
    __syncthreads();
    float r = red[0];
    __syncthreads();
    return r;
}
__device__ __forceinline__ float blk_reduce_max(float v, float* red) {
    int lane = threadIdx.x & 31, w = threadIdx.x >> 5;
#pragma unroll
    for (int o = 16; o; o >>= 1) v = fmaxf(v, __shfl_xor_sync(0xffffffffu, v, o));
    if (lane == 0) red[w] = v;
    __syncthreads();
    if (w == 0) {
        v = (lane < 8) ? red[lane] : -3.4e38f;
#pragma unroll
        for (int o = 4; o; o >>= 1) v = fmaxf(v, __shfl_xor_sync(0xffffffffu, v, o));
        if (lane == 0) red[0] = v;
    }
    __syncthreads();
    float r = red[0];
    __syncthreads();
    return r;
}

// ===========================================================================
// weight rounding (fp32 -> tf32-representable fp32)
// ===========================================================================
__global__ void roundw_kernel(const float* __restrict__ src,
                              float* __restrict__ dst, int n4) {
    int i = blockIdx.x * blockDim.x + threadIdx.x;
    if (i >= n4) return;
    float4 v = ((const float4*)src)[i];
    v.x = round_tf32(v.x); v.y = round_tf32(v.y);
    v.z = round_tf32(v.z); v.w = round_tf32(v.w);
    ((float4*)dst)[i] = v;
}

// ===========================================================================
// adaLN mods
// ===========================================================================
__global__ void mods_kernel(const float* __restrict__ y,
                            const float* __restrict__ w,
                            const float* __restrict__ bias,
                            float* __restrict__ mods) {
    __shared__ float sy[D_];
    int b = blockIdx.x;
    int tid = threadIdx.x;
    float4 yv = ((const float4*)(y + b * D_))[tid];
    sy[tid * 4 + 0] = yv.x / (1.0f + expf(-yv.x));
    sy[tid * 4 + 1] = yv.y / (1.0f + expf(-yv.y));
    sy[tid * 4 + 2] = yv.z / (1.0f + expf(-yv.z));
    sy[tid * 4 + 3] = yv.w / (1.0f + expf(-yv.w));
    __syncthreads();
    int j = blockIdx.y * 256 + tid;
    float acc = bias[j];
    const float4* w4 = (const float4*)(w + (long)j * D_);
#pragma unroll 8
    for (int k = 0; k < D_ / 4; k++) {
        float4 wv = w4[k];
        acc += sy[4 * k + 0] * wv.x + sy[4 * k + 1] * wv.y +
               sy[4 * k + 2] * wv.z + sy[4 * k + 3] * wv.w;
    }
    mods[b * SIXD_ + j] = acc;
}

// ===========================================================================
// LN + modulate (output rounded: feeds GEMM)
// ===========================================================================
__global__ void ln_mod_kernel(const float* __restrict__ X,
                              const float* __restrict__ mods,
                              int sh_off, int sc_off,
                              float* __restrict__ out) {
    __shared__ float red[32];
    long row = blockIdx.x;
    int b = (int)(row >> 10);
    int tid = threadIdx.x;
    float4 v = ((const float4*)(X + row * D_))[tid];
    float s = v.x + v.y + v.z + v.w;
    s = blk_reduce_sum(s, red);
    float mean = s * (1.0f / D_);
    float dx = v.x - mean, dy = v.y - mean, dz = v.z - mean, dw = v.w - mean;
    float sq = dx * dx + dy * dy + dz * dz + dw * dw;
    sq = blk_reduce_sum(sq, red);
    float inv = rsqrtf(sq * (1.0f / D_) + 1e-5f);
    const float* mrow = mods + b * SIXD_;
    int c = tid * 4;
    float4 o;
    o.x = round_tf32(dx * inv * (1.0f + mrow[sc_off + c + 0]) + mrow[sh_off + c + 0]);
    o.y = round_tf32(dy * inv * (1.0f + mrow[sc_off + c + 1]) + mrow[sh_off + c + 1]);
    o.z = round_tf32(dz * inv * (1.0f + mrow[sc_off + c + 2]) + mrow[sh_off + c + 2]);
    o.w = round_tf32(dw * inv * (1.0f + mrow[sc_off + c + 3]) + mrow[sh_off + c + 3]);
    ((float4*)(out + row * D_))[tid] = o;
}

// ===========================================================================
// row softmax (in place, output rounded: feeds PV GEMM)
// ===========================================================================
__global__ void softmax_kernel(float* __restrict__ sc) {
    __shared__ float red[32];
    long row = blockIdx.x;
    float4* p = (float4*)(sc + row * (long)S_);
    int tid = threadIdx.x;
    float4 v = p[tid];
    float mx = fmaxf(fmaxf(v.x, v.y), fmaxf(v.z, v.w));
    mx = blk_reduce_max(mx, red);
    float4 e;
    e.x = expf(v.x - mx); e.y = expf(v.y - mx);
    e.z = expf(v.z - mx); e.w = expf(v.w - mx);
    float s = e.x + e.y + e.z + e.w;
    s = blk_reduce_sum(s, red);
    float inv = 1.0f / s;
    e.x = round_tf32(e.x * inv); e.y = round_tf32(e.y * inv);
    e.z = round_tf32(e.z * inv); e.w = round_tf32(e.w * inv);
    p[tid] = e;
}

// ===========================================================================
// host launcher
// ===========================================================================
extern "C" void kernel_launch(void* const* d_in, const int* in_sizes, int n_in,
                              void* d_out, int out_size) {
    const float* x       = (const float*)d_in[0];
    const float* y       = (const float*)d_in[1];
    const float* w_adaln = (const float*)d_in[2];
    const float* b_adaln = (const float*)d_in[3];
    const float* w_qkv   = (const float*)d_in[4];
    const float* w_proj  = (const float*)d_in[5];
    const float* b_proj  = (const float*)d_in[6];
    const float* b_fc1   = (const float*)d_in[8];
    const float* w_fc1   = (const float*)d_in[7];
    const float* w_fc2   = (const float*)d_in[9];
    const float* b_fc2   = (const float*)d_in[10];
    float* out = (float*)d_out;

    float *mods_p, *xm_p, *qkv_p, *scores_p, *o_p, *h_p, *w_p;
    cudaGetSymbolAddress((void**)&mods_p,   g_mods);
    cudaGetSymbolAddress((void**)&xm_p,     g_xm);
    cudaGetSymbolAddress((void**)&qkv_p,    g_qkv);
    cudaGetSymbolAddress((void**)&scores_p, g_scores);
    cudaGetSymbolAddress((void**)&o_p,      g_o);
    cudaGetSymbolAddress((void**)&h_p,      g_hbuf);
    cudaGetSymbolAddress((void**)&w_p,      g_w);

    float* wq_p = w_p;                       // 3M
    float* wp_p = w_p + 3 * 1024 * 1024;     // 1M
    float* w1_p = w_p + 4 * 1024 * 1024;     // 4M
    float* w2_p = w_p + 8 * 1024 * 1024;     // 4M

    cudaFuncSetAttribute(gemm_mma<0, false, true>,
        cudaFuncAttributeMaxDynamicSharedMemorySize, GM_SMEM);
    cudaFuncSetAttribute(gemm_mma<0, true, true>,
        cudaFuncAttributeMaxDynamicSharedMemorySize, GM_SMEM);
    cudaFuncSetAttribute(gemm_mma<1, false, true>,
        cudaFuncAttributeMaxDynamicSharedMemorySize, GM_SMEM);
    cudaFuncSetAttribute(gemm_mma<2, false, false>,
        cudaFuncAttributeMaxDynamicSharedMemorySize, GM_SMEM);

    const long SQb = (long)S_ * 3 * D_;
    const long SCb = (long)H_ * S_ * S_;
    const long SCh = (long)S_ * S_;

    // 0) round weights to tf32 grid
    roundw_kernel<<<3 * 1024 * 1024 / 4 / 256, 256>>>(w_qkv,  wq_p, 3 * 1024 * 1024 / 4);
    roundw_kernel<<<1 * 1024 * 1024 / 4 / 256, 256>>>(w_proj, wp_p, 1 * 1024 * 1024 / 4);
    roundw_kernel<<<4 * 1024 * 1024 / 4 / 256, 256>>>(w_fc1,  w1_p, 4 * 1024 * 1024 / 4);
    roundw_kernel<<<4 * 1024 * 1024 / 4 / 256, 256>>>(w_fc2,  w2_p, 4 * 1024 * 1024 / 4);

    // 1) adaLN mods
    mods_kernel<<<dim3(B_, SIXD_ / 256), 256>>>(y, w_adaln, b_adaln, mods_p);

    // 2) xm = LN(x)*(1+sc_a)+sh_a   (rounded)
    ln_mod_kernel<<<M_, 256>>>(x, mods_p, 0 * D_, 1 * D_, xm_p);

    // 3) qkv = xm @ w_qkv^T   (rounded out)
    gemm_mma<0, false, true><<<dim3(3 * D_ / 128, M_ / 128, 1), 256, GM_SMEM>>>(
        xm_p, D_, 0, 0, wq_p, D_, 0, 0, qkv_p, 3 * D_, 0, 0,
        3 * D_, D_, 1, 1.0f, nullptr, nullptr, nullptr);

    // 4) scores = 0.125 * q @ k^T per (b,h)   (rounded out)
    gemm_mma<0, false, true><<<dim3(S_ / 128, S_ / 128, B_ * H_), 256, GM_SMEM>>>(
        qkv_p, 3 * D_, SQb, DH_,
        qkv_p + D_, 3 * D_, SQb, DH_,
        scores_p, S_, SCb, SCh,
        S_, DH_, H_, 0.125f, nullptr, nullptr, nullptr);

    // 5) softmax (rounded)
    softmax_kernel<<<B_ * H_ * S_, 256>>>(scores_p);

    // 6) o = attn @ v  (NN, N=64 per head, rounded out)
    gemm_mma<0, true, true><<<dim3(1, S_ / 128, B_ * H_), 256, GM_SMEM>>>(
        scores_p, S_, SCb, SCh,
        qkv_p + 2 * D_, 3 * D_, SQb, DH_,
        o_p, D_, (long)S_ * D_, DH_,
        DH_, S_, H_, 1.0f, nullptr, nullptr, nullptr);

    // 7) x1 = x + g_a * (o @ w_proj^T + b_proj)  -> d_out (fp32)
    gemm_mma<2, false, false><<<dim3(D_ / 128, M_ / 128, 1), 256, GM_SMEM>>>(
        o_p, D_, 0, 0, wp_p, D_, 0, 0, out, D_, 0, 0,
        D_, D_, 1, 1.0f, b_proj, x, mods_p + 2 * D_);

    // 8) xm = LN(x1)*(1+sc_m)+sh_m   (rounded)
    ln_mod_kernel<<<M_, 256>>>(out, mods_p, 3 * D_, 4 * D_, xm_p);

    // 9) h = gelu(xm @ w_fc1^T + b_fc1)   (rounded out)
    gemm_mma<1, false, true><<<dim3(4 * D_ / 128, M_ / 128, 1), 256, GM_SMEM>>>(
        xm_p, D_, 0, 0, w1_p, D_, 0, 0, h_p, 4 * D_, 0, 0,
        4 * D_, D_, 1, 1.0f, b_fc1, nullptr, nullptr);

    // 10) out = x1 + g_m * (h @ w_fc2^T + b_fc2)
    gemm_mma<2, false, false><<<dim3(D_ / 128, M_ / 128, 1), 256, GM_SMEM>>>(
        h_p, 4 * D_, 0, 0, w2_p, 4 * D_, 0, 0, out, D_, 0, 0,
        D_, 4 * D_, 1, 1.0f, b_fc2, out, mods_p + 5 * D_);
}

// round 4
// speedup vs baseline: 3.3351x; 1.2105x over previous
#include <cuda_runtime.h>
#include <cstdint>

// ----------------------------------------------------------------------------
// EBTBlock (DiT adaLN-Zero): B=8, S=1024, D=1024, H=16, DH=64, fp32.
// Round 4: fused flash attention (QK^T -> online softmax -> PV in one kernel,
// P staged via SMEM). Dense GEMMs unchanged (mma.sync tf32, cp.async 2-stage).
// ----------------------------------------------------------------------------

#define B_    8
#define S_    1024
#define D_    1024
#define H_    16
#define DH_   64
#define M_    (B_ * S_)
#define SIXD_ (6 * D_)

// Scratch
__device__ float g_mods[B_ * SIXD_];
__device__ float g_xm[M_ * D_];
__device__ float g_qkv[M_ * 3 * D_];
__device__ float g_o[M_ * D_];
__device__ float g_hbuf[M_ * 4 * D_];
__device__ float g_w[12 * 1024 * 1024];   // rounded weights: qkv|proj|fc1|fc2

// ===========================================================================
// helpers
// ===========================================================================
__device__ __forceinline__ uint32_t smem_u32(const void* p) {
    uint32_t a;
    asm("{ .reg .u64 t; cvta.to.shared.u64 t, %1; cvt.u32.u64 %0, t; }"
        : "=r"(a) : "l"(p));
    return a;
}
__device__ __forceinline__ float round_tf32(float f) {
    uint32_t u;
    asm("cvt.rna.tf32.f32 %0, %1;" : "=r"(u) : "f"(f));
    return __uint_as_float(u);
}
__device__ __forceinline__ void cpasync16(uint32_t dst, const void* src) {
    asm volatile("cp.async.ca.shared.global [%0], [%1], 16;"
                 :: "r"(dst), "l"(src) : "memory");
}
__device__ __forceinline__ void mma_tf32(float* d, const uint32_t* a,
                                         const uint32_t* b) {
    asm volatile(
        "mma.sync.aligned.m16n8k8.row.col.f32.tf32.tf32.f32 "
        "{%0,%1,%2,%3}, {%4,%5,%6,%7}, {%8,%9}, {%0,%1,%2,%3};"
        : "+f"(d[0]), "+f"(d[1]), "+f"(d[2]), "+f"(d[3])
        : "r"(a[0]), "r"(a[1]), "r"(a[2]), "r"(a[3]), "r"(b[0]), "r"(b[1]));
}
__device__ __forceinline__ float gelu_tanh(float x) {
    float x3 = x * x * x;
    float t = tanhf(0.7978845608028654f * (x + 0.044715f * x3));
    return 0.5f * x * (1.0f + t);
}

// ===========================================================================
// Fused flash attention.  grid (S/128, B*H), 256 thr (8 warps, warp = 16 rows)
// qkv: [B*S, 3D]; writes O (head-interleaved [B,S,D]), rounded tf32.
// SMEM: Q[128][68] K[128][68] V[128][72] P[128][132]  = 170 KB
// ===========================================================================
#define QS_STR 68
#define VS_STR 72
#define PS_STR 132
#define FA_SMEM ((128 * QS_STR * 2 + 128 * VS_STR + 128 * PS_STR) * 4)

__global__ __launch_bounds__(256, 1)
void flash_kernel(const float* __restrict__ qkv, float* __restrict__ O) {
    extern __shared__ float fs[];
    float* Qs = fs;
    float* Ks = Qs + 128 * QS_STR;
    float* Vs = Ks + 128 * QS_STR;
    float* Ps = Vs + 128 * VS_STR;
    const uint32_t sbK = smem_u32(Ks), sbV = smem_u32(Vs);
    const uint32_t* Qu = (const uint32_t*)Qs;
    const uint32_t* Ku = (const uint32_t*)Ks;
    const uint32_t* Vu = (const uint32_t*)Vs;
    const uint32_t* Pu = (const uint32_t*)Ps;

    const int tid = threadIdx.x, lane = tid & 31, wid = tid >> 5;
    const int q = lane & 3, lh = lane >> 2;
    const int w16 = wid * 16;
    const int bh = blockIdx.y, bb = bh >> 4, hh = bh & 15;
    const int q0 = blockIdx.x * 128;
    const size_t base = (size_t)bb * S_ * 3 * D_ + (size_t)hh * DH_;

    // load Q (scaled by 1/sqrt(DH)=0.125, exact) into smem
#pragma unroll
    for (int it = 0; it < 8; it++) {
        int idx = tid + it * 256;
        int r = idx >> 4, c4 = (idx & 15) << 2;
        float4 v = *(const float4*)(qkv + base + (size_t)(q0 + r) * 3 * D_ + c4);
        v.x *= 0.125f; v.y *= 0.125f; v.z *= 0.125f; v.w *= 0.125f;
        *(float4*)(Qs + r * QS_STR + c4) = v;
    }

    float accO[8][4];
#pragma unroll
    for (int j = 0; j < 8; j++)
#pragma unroll
        for (int e = 0; e < 4; e++) accO[j][e] = 0.0f;
    float mstate[2] = {-1e30f, -1e30f};
    float lstate[2] = {0.0f, 0.0f};

    for (int t = 0; t < 8; t++) {
        const int kv0 = t * 128;
        // load K, V tiles
#pragma unroll
        for (int it = 0; it < 8; it++) {
            int idx = tid + it * 256;
            int r = idx >> 4, c4 = (idx & 15) << 2;
            const float* gk = qkv + base + D_ + (size_t)(kv0 + r) * 3 * D_ + c4;
            cpasync16(sbK + (uint32_t)(r * QS_STR + c4) * 4, gk);
            cpasync16(sbV + (uint32_t)(r * VS_STR + c4) * 4, gk + D_);
        }
        asm volatile("cp.async.commit_group;" ::: "memory");
        asm volatile("cp.async.wait_group 0;" ::: "memory");
        __syncthreads();

        // S = Qs @ Ks^T   (warp tile 16 x 128)
        float sc[16][4];
#pragma unroll
        for (int j = 0; j < 16; j++)
#pragma unroll
            for (int e = 0; e < 4; e++) sc[j][e] = 0.0f;
#pragma unroll
        for (int kk = 0; kk < 64; kk += 8) {
            uint32_t a[4];
            a[0] = Qu[(w16 + lh) * QS_STR + kk + q];
            a[1] = Qu[(w16 + lh + 8) * QS_STR + kk + q];
            a[2] = Qu[(w16 + lh) * QS_STR + kk + q + 4];
            a[3] = Qu[(w16 + lh + 8) * QS_STR + kk + q + 4];
#pragma unroll
            for (int j = 0; j < 16; j++) {
                uint32_t b[2];
                b[0] = Ku[(j * 8 + lh) * QS_STR + kk + q];
                b[1] = Ku[(j * 8 + lh) * QS_STR + kk + q + 4];
                mma_tf32(sc[j], a, b);
            }
        }

        // online softmax per row pair
#pragma unroll
        for (int h2 = 0; h2 < 2; h2++) {
            float mx = -1e30f;
#pragma unroll
            for (int j = 0; j < 16; j++)
                mx = fmaxf(mx, fmaxf(sc[j][h2 * 2], sc[j][h2 * 2 + 1]));
            mx = fmaxf(mx, __shfl_xor_sync(0xffffffffu, mx, 1));
            mx = fmaxf(mx, __shfl_xor_sync(0xffffffffu, mx, 2));
            float mn = fmaxf(mstate[h2], mx);
            float f = __expf(mstate[h2] - mn);
            mstate[h2] = mn;
            float rs = 0.0f;
#pragma unroll
            for (int j = 0; j < 16; j++) {
#pragma unroll
                for (int e = 0; e < 2; e++) {
                    float p = round_tf32(__expf(sc[j][h2 * 2 + e] - mn));
                    rs += p;
                    sc[j][h2 * 2 + e] = p;
                }
            }
            rs += __shfl_xor_sync(0xffffffffu, rs, 1);
            rs += __shfl_xor_sync(0xffffffffu, rs, 2);
            lstate[h2] = lstate[h2] * f + rs;
#pragma unroll
            for (int j = 0; j < 8; j++) {
                accO[j][h2 * 2] *= f;
                accO[j][h2 * 2 + 1] *= f;
            }
        }

        // stage P to smem
#pragma unroll
        for (int j = 0; j < 16; j++) {
#pragma unroll
            for (int h2 = 0; h2 < 2; h2++) {
                float2 pv = make_float2(sc[j][h2 * 2], sc[j][h2 * 2 + 1]);
                *(float2*)(Ps + (w16 + lh + 8 * h2) * PS_STR + j * 8 + 2 * q) = pv;
            }
        }
        __syncthreads();

        // O += P @ V   (warp tile 16 x 64, K = 128)
#pragma unroll
        for (int kb = 0; kb < 16; kb++) {
            uint32_t a[4];
            a[0] = Pu[(w16 + lh) * PS_STR + kb * 8 + q];
            a[1] = Pu[(w16 + lh + 8) * PS_STR + kb * 8 + q];
            a[2] = Pu[(w16 + lh) * PS_STR + kb * 8 + q + 4];
            a[3] = Pu[(w16 + lh + 8) * PS_STR + kb * 8 + q + 4];
#pragma unroll
            for (int j = 0; j < 8; j++) {
                uint32_t b[2];
                b[0] = Vu[(kb * 8 + q) * VS_STR + j * 8 + lh];
                b[1] = Vu[(kb * 8 + q + 4) * VS_STR + j * 8 + lh];
                mma_tf32(accO[j], a, b);
            }
        }
        __syncthreads();   // protect K/V/P for next tile's loads
    }

    // write O (rounded, feeds proj GEMM)
    float inv0 = 1.0f / lstate[0], inv1 = 1.0f / lstate[1];
#pragma unroll
    for (int h2 = 0; h2 < 2; h2++) {
        float inv = h2 ? inv1 : inv0;
        size_t row = (size_t)(bb * S_ + q0 + w16 + lh + 8 * h2);
#pragma unroll
        for (int j = 0; j < 8; j++) {
            float2 o;
            o.x = round_tf32(accO[j][h2 * 2] * inv);
            o.y = round_tf32(accO[j][h2 * 2 + 1] * inv);
            *(float2*)(O + row * D_ + hh * DH_ + j * 8 + 2 * q) = o;
        }
    }
}

// ===========================================================================
// dense tf32 mma GEMM (NT), 128x128 tile, cp.async 2-stage (unchanged core)
// ===========================================================================
#define GM_SMEM 73728
#define STG_F   9216
#define STRA    36

template <int EPI, bool RND>
__global__ __launch_bounds__(256, 2)
void gemm_mma(const float* __restrict__ A, int lda,
              const float* __restrict__ Bw, int ldb,
              float* __restrict__ C, int ldc,
              int K, float alpha,
              const float* __restrict__ bias,
              const float* __restrict__ resid,
              const float* __restrict__ gate) {
    extern __shared__ float smem[];
    const int tid = threadIdx.x, lane = tid & 31, wid = tid >> 5;
    const int wm = wid & 3, wn = wid >> 2;
    const int m0 = blockIdx.y * 128, n0 = blockIdx.x * 128;
    const uint32_t sbase = smem_u32(smem);

    float acc[2][8][4];
#pragma unroll
    for (int i = 0; i < 2; i++)
#pragma unroll
        for (int j = 0; j < 8; j++)
#pragma unroll
            for (int e = 0; e < 4; e++) acc[i][j][e] = 0.0f;

    const int nch = K >> 5;

    auto load_stage = [&](int s, int k0) {
#pragma unroll
        for (int it = 0; it < 4; it++) {
            int idx = tid + it * 256;
            int r = idx >> 3, c4 = (idx & 7) << 2;
            cpasync16(sbase + (uint32_t)(s * STG_F + r * STRA + c4) * 4,
                      A + (size_t)(m0 + r) * lda + k0 + c4);
            cpasync16(sbase + (uint32_t)(s * STG_F + 4608 + r * STRA + c4) * 4,
                      Bw + (size_t)(n0 + r) * ldb + k0 + c4);
        }
    };

    load_stage(0, 0);
    asm volatile("cp.async.commit_group;" ::: "memory");

    const int q = lane & 3, lh = lane >> 2;

    for (int i = 0; i < nch; i++) {
        if (i + 1 < nch) {
            load_stage((i + 1) & 1, (i + 1) << 5);
            asm volatile("cp.async.commit_group;" ::: "memory");
            asm volatile("cp.async.wait_group 1;" ::: "memory");
        } else {
            asm volatile("cp.async.wait_group 0;" ::: "memory");
        }
        __syncthreads();

        const uint32_t* sA = (const uint32_t*)(smem + (i & 1) * STG_F);
        const uint32_t* sB = sA + 4608;
#pragma unroll
        for (int kk = 0; kk < 32; kk += 8) {
            uint32_t a[2][4], b[8][2];
#pragma unroll
            for (int ii = 0; ii < 2; ii++) {
                int rowA = wm * 32 + ii * 16 + lh;
                a[ii][0] = sA[rowA * STRA + kk + q];
                a[ii][1] = sA[(rowA + 8) * STRA + kk + q];
                a[ii][2] = sA[rowA * STRA + kk + q + 4];
                a[ii][3] = sA[(rowA + 8) * STRA + kk + q + 4];
            }
#pragma unroll
            for (int j = 0; j < 8; j++) {
                int nn = wn * 64 + j * 8 + lh;
                b[j][0] = sB[nn * STRA + kk + q];
                b[j][1] = sB[nn * STRA + kk + q + 4];
            }
#pragma unroll
            for (int ii = 0; ii < 2; ii++)
#pragma unroll
                for (int j = 0; j < 8; j++)
                    mma_tf32(acc[ii][j], a[ii], b[j]);
        }
        __syncthreads();
    }

#pragma unroll
    for (int ii = 0; ii < 2; ii++) {
        int gm0 = m0 + wm * 32 + ii * 16 + lh;
#pragma unroll
        for (int j = 0; j < 8; j++) {
            int gn = n0 + wn * 64 + j * 8 + 2 * q;
#pragma unroll
            for (int h = 0; h < 2; h++) {
                int gm = gm0 + h * 8;
                float2 o;
                float* ov = &o.x;
#pragma unroll
                for (int e = 0; e < 2; e++) {
                    float v = acc[ii][j][h * 2 + e] * alpha;
                    int n = gn + e;
                    if (EPI == 1) {
                        v = gelu_tanh(v + bias[n]);
                    } else if (EPI == 2) {
                        v = resid[(size_t)gm * ldc + n] +
                            gate[(size_t)(gm >> 10) * SIXD_ + n] * (v + bias[n]);
                    }
                    if (RND) v = round_tf32(v);
                    ov[e] = v;
                }
                *(float2*)(C + (size_t)gm * ldc + gn) = o;
            }
        }
    }
}

// ===========================================================================
// block reductions / small kernels
// ===========================================================================
__device__ __forceinline__ float blk_reduce_sum(float v, float* red) {
    int lane = threadIdx.x & 31, w = threadIdx.x >> 5;
#pragma unroll
    for (int o = 16; o; o >>= 1) v += __shfl_xor_sync(0xffffffffu, v, o);
    if (lane == 0) red[w] = v;
    __syncthreads();
    if (w == 0) {
        v = (lane < 8) ? red[lane] : 0.0f;
#pragma unroll
        for (int o = 4; o; o >>= 1) v += __shfl_xor_sync(0xffffffffu, v, o);
        if (lane == 0) red[0] = v;
    }
    __syncthreads();
    float r = red[0];
    __syncthreads();
    return r;
}

__global__ void roundw_kernel(const float* __restrict__ src,
                              float* __restrict__ dst, int n4) {
    int i = blockIdx.x * blockDim.x + threadIdx.x;
    if (i >= n4) return;
    float4 v = ((const float4*)src)[i];
    v.x = round_tf32(v.x); v.y = round_tf32(v.y);
    v.z = round_tf32(v.z); v.w = round_tf32(v.w);
    ((float4*)dst)[i] = v;
}

__global__ void mods_kernel(const float* __restrict__ y,
                            const float* __restrict__ w,
                            const float* __restrict__ bias,
                            float* __restrict__ mods) {
    __shared__ float sy[D_];
    int b = blockIdx.x;
    int tid = threadIdx.x;
    float4 yv = ((const float4*)(y + b * D_))[tid];
    sy[tid * 4 + 0] = yv.x / (1.0f + expf(-yv.x));
    sy[tid * 4 + 1] = yv.y / (1.0f + expf(-yv.y));
    sy[tid * 4 + 2] = yv.z / (1.0f + expf(-yv.z));
    sy[tid * 4 + 3] = yv.w / (1.0f + expf(-yv.w));
    __syncthreads();
    int j = blockIdx.y * 256 + tid;
    float acc = bias[j];
    const float4* w4 = (const float4*)(w + (long)j * D_);
#pragma unroll 8
    for (int k = 0; k < D_ / 4; k++) {
        float4 wv = w4[k];
        acc += sy[4 * k + 0] * wv.x + sy[4 * k + 1] * wv.y +
               sy[4 * k + 2] * wv.z + sy[4 * k + 3] * wv.w;
    }
    mods[b * SIXD_ + j] = acc;
}

__global__ void ln_mod_kernel(const float* __restrict__ X,
                              const float* __restrict__ mods,
                              int sh_off, int sc_off,
                              float* __restrict__ out) {
    __shared__ float red[32];
    long row = blockIdx.x;
    int b = (int)(row >> 10);
    int tid = threadIdx.x;
    float4 v = ((const float4*)(X + row * D_))[tid];
    float s = v.x + v.y + v.z + v.w;
    s = blk_reduce_sum(s, red);
    float mean = s * (1.0f / D_);
    float dx = v.x - mean, dy = v.y - mean, dz = v.z - mean, dw = v.w - mean;
    float sq = dx * dx + dy * dy + dz * dz + dw * dw;
    sq = blk_reduce_sum(sq, red);
    float inv = rsqrtf(sq * (1.0f / D_) + 1e-5f);
    const float* mrow = mods + b * SIXD_;
    int c = tid * 4;
    float4 o;
    o.x = round_tf32(dx * inv * (1.0f + mrow[sc_off + c + 0]) + mrow[sh_off + c + 0]);
    o.y = round_tf32(dy * inv * (1.0f + mrow[sc_off + c + 1]) + mrow[sh_off + c + 1]);
    o.z = round_tf32(dz * inv * (1.0f + mrow[sc_off + c + 2]) + mrow[sh_off + c + 2]);
    o.w = round_tf32(dw * inv * (1.0f + mrow[sc_off + c + 3]) + mrow[sh_off + c + 3]);
    ((float4*)(out + row * D_))[tid] = o;
}

// ===========================================================================
// host launcher
// ===========================================================================
extern "C" void kernel_launch(void* const* d_in, const int* in_sizes, int n_in,
                              void* d_out, int out_size) {
    const float* x       = (const float*)d_in[0];
    const float* y       = (const float*)d_in[1];
    const float* w_adaln = (const float*)d_in[2];
    const float* b_adaln = (const float*)d_in[3];
    const float* w_qkv   = (const float*)d_in[4];
    const float* w_proj  = (const float*)d_in[5];
    const float* b_proj  = (const float*)d_in[6];
    const float* w_fc1   = (const float*)d_in[7];
    const float* b_fc1   = (const float*)d_in[8];
    const float* w_fc2   = (const float*)d_in[9];
    const float* b_fc2   = (const float*)d_in[10];
    float* out = (float*)d_out;

    float *mods_p, *xm_p, *qkv_p, *o_p, *h_p, *w_p;
    cudaGetSymbolAddress((void**)&mods_p, g_mods);
    cudaGetSymbolAddress((void**)&xm_p,   g_xm);
    cudaGetSymbolAddress((void**)&qkv_p,  g_qkv);
    cudaGetSymbolAddress((void**)&o_p,    g_o);
    cudaGetSymbolAddress((void**)&h_p,    g_hbuf);
    cudaGetSymbolAddress((void**)&w_p,    g_w);

    float* wq_p = w_p;
    float* wp_p = w_p + 3 * 1024 * 1024;
    float* w1_p = w_p + 4 * 1024 * 1024;
    float* w2_p = w_p + 8 * 1024 * 1024;

    cudaFuncSetAttribute(gemm_mma<0, true>,
        cudaFuncAttributeMaxDynamicSharedMemorySize, GM_SMEM);
    cudaFuncSetAttribute(gemm_mma<1, true>,
        cudaFuncAttributeMaxDynamicSharedMemorySize, GM_SMEM);
    cudaFuncSetAttribute(gemm_mma<2, false>,
        cudaFuncAttributeMaxDynamicSharedMemorySize, GM_SMEM);
    cudaFuncSetAttribute(flash_kernel,
        cudaFuncAttributeMaxDynamicSharedMemorySize, FA_SMEM);

    // 0) round weights to tf32 grid
    roundw_kernel<<<3 * 1024 * 1024 / 4 / 256, 256>>>(w_qkv,  wq_p, 3 * 1024 * 1024 / 4);
    roundw_kernel<<<1 * 1024 * 1024 / 4 / 256, 256>>>(w_proj, wp_p, 1 * 1024 * 1024 / 4);
    roundw_kernel<<<4 * 1024 * 1024 / 4 / 256, 256>>>(w_fc1,  w1_p, 4 * 1024 * 1024 / 4);
    roundw_kernel<<<4 * 1024 * 1024 / 4 / 256, 256>>>(w_fc2,  w2_p, 4 * 1024 * 1024 / 4);

    // 1) adaLN mods
    mods_kernel<<<dim3(B_, SIXD_ / 256), 256>>>(y, w_adaln, b_adaln, mods_p);

    // 2) xm = LN(x)*(1+sc_a)+sh_a (rounded)
    ln_mod_kernel<<<M_, 256>>>(x, mods_p, 0 * D_, 1 * D_, xm_p);

    // 3) qkv = xm @ w_qkv^T (rounded out)
    gemm_mma<0, true><<<dim3(3 * D_ / 128, M_ / 128), 256, GM_SMEM>>>(
        xm_p, D_, wq_p, D_, qkv_p, 3 * D_, D_, 1.0f, nullptr, nullptr, nullptr);

    // 4) fused attention -> o (rounded)
    flash_kernel<<<dim3(S_ / 128, B_ * H_), 256, FA_SMEM>>>(qkv_p, o_p);

    // 5) x1 = x + g_a * (o @ w_proj^T + b_proj) -> d_out (fp32)
    gemm_mma<2, false><<<dim3(D_ / 128, M_ / 128), 256, GM_SMEM>>>(
        o_p, D_, wp_p, D_, out, D_, D_, 1.0f, b_proj, x, mods_p + 2 * D_);

    // 6) xm = LN(x1)*(1+sc_m)+sh_m (rounded)
    ln_mod_kernel<<<M_, 256>>>(out, mods_p, 3 * D_, 4 * D_, xm_p);

    // 7) h = gelu(xm @ w_fc1^T + b_fc1) (rounded out)
    gemm_mma<1, true><<<dim3(4 * D_ / 128, M_ / 128), 256, GM_SMEM>>>(
        xm_p, D_, w1_p, D_, h_p, 4 * D_, D_, 1.0f, b_fc1, nullptr, nullptr);

    // 8) out = x1 + g_m * (h @ w_fc2^T + b_fc2)
    gemm_mma<2, false><<<dim3(D_ / 128, M_ / 128), 256, GM_SMEM>>>(
        h_p, 4 * D_, w2_p, 4 * D_, out, D_, 4 * D_, 1.0f, b_fc2, out, mods_p + 5 * D_);
}